// round 8
// baseline (speedup 1.0000x reference)
#include <cuda_runtime.h>
#include <cstdint>

#define BB 32
#define JJ 256
#define MM 128
#define DD 200
#define NTH 512
#define CH 25            // d-chunk per rank
#define CSZ 8            // cluster size
#define MPAD 27          // padded mem row stride (27 coprime 32)
#define MEMBK 3456       // per-bank floats (128 * 27)
#define MEMLN 6912       // per-lane mem floats (2 banks)

// ---------------- persistent transposed weight scratch (fp32) ----------------
__device__ __align__(16) float g_wTg[400 * 800];   // [k][4*d+g], k<200 ih else hh
__device__ __align__(16) float g_wTfc1[400 * 200]; // [k][d], k: x then q
__device__ __align__(16) float g_wTfc[200 * 200];  // [k][d]
__device__ __align__(16) float g_bg[800];          // b_ih+b_hh gate-interleaved

__global__ void prep_kernel(const float* __restrict__ w_fc, const float* __restrict__ w_fc1,
                            const float* __restrict__ w_ih, const float* __restrict__ w_hh,
                            const float* __restrict__ b_ih, const float* __restrict__ b_hh)
{
    int stride = gridDim.x * blockDim.x;
    int i0 = blockIdx.x * blockDim.x + threadIdx.x;

    for (int idx = i0; idx < 400 * 800; idx += stride) {
        int k = idx / 800, rem = idx % 800;
        int d = rem >> 2, g = rem & 3;
        int o = g * 200 + d;
        g_wTg[idx] = (k < 200) ? w_ih[o * 200 + k] : w_hh[o * 200 + (k - 200)];
    }
    for (int idx = i0; idx < 800; idx += stride) {
        int d = idx >> 2, g = idx & 3;
        int o = g * 200 + d;
        g_bg[idx] = b_ih[o] + b_hh[o];
    }
    for (int idx = i0; idx < 400 * 200; idx += stride) {
        int k = idx / 200, d = idx % 200;
        g_wTfc1[idx] = w_fc1[d * 400 + k];
    }
    for (int idx = i0; idx < 200 * 200; idx += stride) {
        int k = idx / 200, d = idx % 200;
        g_wTfc[idx] = w_fc[d * 200 + k];
    }
}

__device__ __forceinline__ float sigf(float v) { return 1.0f / (1.0f + __expf(-v)); }
__device__ __forceinline__ float ftanh(float x) { return 1.0f - 2.0f / (__expf(2.0f * x) + 1.0f); }

__device__ __forceinline__ void cluster_bar()
{
    asm volatile("barrier.cluster.arrive.aligned;\n\t"
                 "barrier.cluster.wait.aligned;" ::: "memory");
}
__device__ __forceinline__ void st_peer(uint32_t laddr, uint32_t peer, float v)
{
    uint32_t r;
    asm volatile("mapa.shared::cluster.u32 %0, %1, %2;" : "=r"(r) : "r"(laddr), "r"(peer));
    asm volatile("st.shared::cluster.f32 [%0], %1;" :: "r"(r), "f"(v) : "memory");
}
__device__ __forceinline__ void st_peer_v2(uint32_t laddr, uint32_t peer, float a, float b)
{
    uint32_t r;
    unsigned long long v = (unsigned long long)__float_as_uint(a) |
                           ((unsigned long long)__float_as_uint(b) << 32);
    asm volatile("mapa.shared::cluster.u32 %0, %1, %2;" : "=r"(r) : "r"(laddr), "r"(peer));
    asm volatile("st.shared::cluster.b64 [%0], %1;" :: "r"(r), "l"(v) : "memory");
}
__device__ __forceinline__ void st_peer_v4(uint32_t laddr, uint32_t peer, float4 v)
{
    uint32_t r;
    unsigned long long lo = (unsigned long long)__float_as_uint(v.x) |
                            ((unsigned long long)__float_as_uint(v.y) << 32);
    unsigned long long hi = (unsigned long long)__float_as_uint(v.z) |
                            ((unsigned long long)__float_as_uint(v.w) << 32);
    asm volatile("mapa.shared::cluster.u32 %0, %1, %2;" : "=r"(r) : "r"(laddr), "r"(peer));
    asm volatile("st.shared::cluster.b64 [%0], %1;" :: "r"(r), "l"(lo) : "memory");
    asm volatile("st.shared::cluster.b64 [%0+8], %1;" :: "r"(r), "l"(hi) : "memory");
}

// ---------------- SMEM layout (float indices), 2 lanes, CSZ=8 ----------------
#define SM_MEM   0                      // mem[2 ln][2 bank][128][27] = 13824
#define SM_PART  13824                  // part[ln][1600] = 3200
#define SM_GP    17024                  // gparts[ln][8 src][100] = 1600
#define SM_ATTP  18624                  // attp[ln][8 src][128] = 2048
#define SM_QP    20672                  // qparts[ln][8 src][25] = 400
#define SM_ZP    21072                  // zparts[ln][8 src][25] = 400
#define SM_ATT   21472                  // att[ln][128] = 256
#define SM_RED   21728                  // red[ln][8] = 16
#define SM_XV    21744                  // xv[ln][32] = 64
#define SM_CS    21808                  // cstage[buf][ln][128] = 512
#define SM_BJ    22320                  // bstage[buf][ln][200] = 800
#define SM_QL    23120                  // qloc[ln][32] = 64
#define SM_HL    23184                  // hloc[ln][32] = 64
#define SM_CV    23248                  // cvec[ln][32] = 64
#define SM_BG    23312                  // bgs[112] (100 used)
#define SM_BFC   23424                  // bfcs[32]
#define SM_BFC1  23456                  // bfc1s[32]
#define SM_TOT   23488                  // 93952 bytes

__global__ void __launch_bounds__(NTH, 1) __cluster_dims__(CSZ, 1, 1)
speaker_kernel(const float* __restrict__ cosp, const float* __restrict__ bank,
               const float* __restrict__ mem_a, const float* __restrict__ mem_b,
               const float* __restrict__ b_fc, const float* __restrict__ b_fc1,
               float* __restrict__ out)
{
    extern __shared__ float sm[];
    float* bgs   = sm + SM_BG;
    float* bfcs  = sm + SM_BFC;
    float* bfc1s = sm + SM_BFC1;

    const int tid  = threadIdx.x;
    const int lane0 = (blockIdx.x >> 3) * 2;   // first batch lane of this cluster
    const uint32_t rank = blockIdx.x & 7;      // owns d-chunk [25r, 25r+25)
    const int cbase = (int)rank * CH;
    const uint32_t sb = (uint32_t)__cvta_generic_to_shared(sm);

    // ---- init: biases, mem chunks (both lanes), first-step staging ----
    if (tid < 112) bgs[tid] = g_bg[rank * 100 + min(tid, 99)];
    if (tid < CH) { bfcs[tid] = b_fc[cbase + tid]; bfc1s[tid] = b_fc1[cbase + tid]; }
    for (int idx = tid; idx < 2 * MM * CH; idx += NTH) {
        int ln = idx / (MM * CH), r2 = idx % (MM * CH);
        int m = r2 / CH, d = r2 % CH;
        sm[SM_MEM + ln * MEMLN + m * MPAD + d] =
            mem_a[(lane0 + ln) * MM * DD + m * DD + cbase + d];
        sm[SM_MEM + ln * MEMLN + MEMBK + m * MPAD + d] =
            mem_b[(lane0 + ln) * MM * DD + m * DD + cbase + d];
    }
    for (int i = tid; i < 2 * MM; i += NTH) {
        int ln = i >> 7, t = i & 127;
        sm[SM_CS + ln * 128 + t] = cosp[((lane0 + ln) * JJ + 0) * MM + t];
    }
    for (int i = tid; i < 2 * DD; i += NTH) {
        int ln = i / DD, t = i % DD;
        sm[SM_BJ + ln * 200 + t] = bank[(0 * BB + lane0 + ln) * DD + t];
    }
    __syncthreads();
    cluster_bar();

    for (int j = 0; j < JJ; ++j) {
        const int flag = j & 1;
        const int slot = j >> 1;
        const int jb = j & 1;
        float* mem0 = sm + SM_MEM + flag * MEMBK;
        float* mem1 = sm + SM_MEM + MEMLN + flag * MEMBK;
        const float* cs0 = sm + SM_CS + jb * 256;
        const float* cs1 = cs0 + 128;
        const float* bj0 = sm + SM_BJ + jb * 400;
        const float* bj1 = bj0 + 200;

        // ---- P1: q-init GEMV (dual-lane fused, col-split: rank's 25 channels)
        //          + h-init chunk partials (per-lane, 4 m-segs x 25 d) ----
        if (tid < 200) {
            int ks = tid / 25, c = tid % 25;
            int k0 = ks * 25;
            const float* W = g_wTfc + cbase + c;
            float a0 = 0.f, a1 = 0.f;
            #pragma unroll 5
            for (int i = 0; i < 25; ++i) {
                float w = W[(k0 + i) * 200];
                a0 += bj0[k0 + i] * w;
                a1 += bj1[k0 + i] * w;
            }
            sm[SM_PART + ks * 25 + c] = a0;
            sm[SM_PART + 1600 + ks * 25 + c] = a1;
        } else if (tid < 400) {
            int t = tid - 200;
            int ln = t / 100, r2 = t % 100;
            int seg = r2 / 25, d = r2 % 25;
            const float* mp = (ln ? mem1 : mem0) + (seg * 32) * MPAD + d;
            const float* cj = (ln ? cs1 : cs0) + seg * 32;
            float a = 0.f;
            #pragma unroll 8
            for (int m = 0; m < 32; ++m) a += cj[m] * mp[m * MPAD];
            sm[SM_PART + ln * 1600 + 256 + seg * 25 + d] = a;
        }
        __syncthreads();
        // ---- P2: combine q (8 ks) + h (4 segs) + reset c; one guard ----
        {
            int r = tid & 255;
            if (r < CH && tid < 256 + CH) {
                int ln = tid >> 8;
                const float* pp = sm + SM_PART + ln * 1600;
                float a = bfcs[r];
                #pragma unroll
                for (int ks = 0; ks < 8; ++ks) a += pp[ks * 25 + r];
                sm[SM_QL + ln * 32 + r] = a;
                sm[SM_HL + ln * 32 + r] = pp[256 + r] + pp[281 + r] + pp[306 + r] + pp[331 + r];
                sm[SM_CV + ln * 32 + r] = 0.0f;
            }
        }
        __syncthreads();

        // ---------------- inner loop P=3 ----------------
        for (int p = 0; p < 3; ++p) {
            // G0: gates GEMV, k-local (rank's 25 q-k + 25 h-k), dual-lane fused.
            // 2 ks x 200 float4 cols; idle threads prefetch next stage on p==0.
            if (tid < 400) {
                int ks = tid / 200, c = tid % 200;
                const float4* W4 = reinterpret_cast<const float4*>(g_wTg)
                                   + (ks ? (200 + cbase) : cbase) * 200 + c;
                const float* a0p = sm + (ks ? SM_HL : SM_QL);
                const float* a1p = a0p + 32;
                float4 s0 = make_float4(0.f, 0.f, 0.f, 0.f);
                float4 s1 = make_float4(0.f, 0.f, 0.f, 0.f);
                #pragma unroll 5
                for (int i = 0; i < CH; ++i) {
                    float4 w = W4[i * 200];
                    float v0 = a0p[i], v1 = a1p[i];
                    s0.x += v0 * w.x; s0.y += v0 * w.y; s0.z += v0 * w.z; s0.w += v0 * w.w;
                    s1.x += v1 * w.x; s1.y += v1 * w.y; s1.z += v1 * w.z; s1.w += v1 * w.w;
                }
                reinterpret_cast<float4*>(sm + SM_PART)[ks * 200 + c] = s0;
                reinterpret_cast<float4*>(sm + SM_PART + 1600)[ks * 200 + c] = s1;
            } else if (p == 0 && j + 1 < JJ) {
                int nj = j + 1, nb = nj & 1, t = tid - 400;
                for (int i = t; i < MM; i += 112) {
                    sm[SM_CS + nb * 256 + i]       = cosp[(lane0 * JJ + nj) * MM + i];
                    sm[SM_CS + nb * 256 + 128 + i] = cosp[((lane0 + 1) * JJ + nj) * MM + i];
                }
                for (int i = t; i < DD; i += 112) {
                    sm[SM_BJ + nb * 400 + i]       = bank[(nj * BB + lane0) * DD + i];
                    sm[SM_BJ + nb * 400 + 200 + i] = bank[(nj * BB + lane0 + 1) * DD + i];
                }
            }
            __syncthreads();
            // G0b: combine 2 ks + deposit gate-quad to owning rank (both lanes)
            {
                int r = tid & 255;
                if (r < 200 && tid < 456) {
                    int ln = tid >> 8;
                    const float4* p4 = reinterpret_cast<const float4*>(sm + SM_PART + ln * 1600);
                    float4 a = p4[r], b = p4[200 + r];
                    float4 v = make_float4(a.x + b.x, a.y + b.y, a.z + b.z, a.w + b.w);
                    int owner = r / CH, loc = r % CH;
                    uint32_t off = SM_GP + ln * 800 + rank * 100 + loc * 4;
                    if (owner == (int)rank) *reinterpret_cast<float4*>(sm + off) = v;
                    else st_peer_v4(sb + 4u * off, (uint32_t)owner, v);
                }
            }
            cluster_bar();   // Bg
            // G1: reduce 8 sources + LSTM (quad-parallel; lane0 warps 0-3, lane1 warps 8-11)
            {
                int r = tid & 255;
                if (r < 128 && tid < 384) {
                    int ln = tid >> 8;
                    int t = min(r, 99);
                    int chl = t >> 2, gi = t & 3;
                    const float* gp = sm + SM_GP + ln * 800;
                    float g = bgs[t];
                    #pragma unroll
                    for (int s = 0; s < 8; ++s) g += gp[s * 100 + t];
                    float val = (gi == 2) ? ftanh(g) : sigf(g);
                    float ig = __shfl_sync(0xffffffffu, val, 0, 4);
                    float fg = __shfl_sync(0xffffffffu, val, 1, 4);
                    float gg = __shfl_sync(0xffffffffu, val, 2, 4);
                    float og = __shfl_sync(0xffffffffu, val, 3, 4);
                    if (r < 100 && gi == 0) {
                        float cc = fg * sm[SM_CV + ln * 32 + chl] + ig * gg;
                        sm[SM_CV + ln * 32 + chl] = cc;
                        sm[SM_HL + ln * 32 + chl] = og * ftanh(cc);
                    }
                }
            }
            __syncthreads();
            // G2: attention logit partials over local 25-d chunk (1 thread per m)
            {
                int r = tid & 255;
                if (r < 128 && tid < 384) {
                    int ln = tid >> 8;
                    const float* mrow = (ln ? mem1 : mem0) + r * MPAD;
                    const float* hl = sm + SM_HL + ln * 32;
                    float a = 0.f;
                    #pragma unroll 5
                    for (int i = 0; i < CH; ++i) a += hl[i] * mrow[i];
                    sm[SM_PART + ln * 1600 + r] = a;
                }
            }
            __syncthreads();
            // G2b: push logit partials (float2-packed) to self + 7 peers
            {
                int r = tid & 255;
                if (r < 64 && tid < 320) {
                    int ln = tid >> 8;
                    const float* pp = sm + SM_PART + ln * 1600;
                    float a = pp[r * 2], b = pp[r * 2 + 1];
                    uint32_t off = SM_ATTP + ln * 1024 + rank * 128 + r * 2;
                    *reinterpret_cast<float2*>(sm + off) = make_float2(a, b);
                    #pragma unroll
                    for (uint32_t pr = 1; pr < CSZ; ++pr)
                        st_peer_v2(sb + 4u * off, (rank + pr) & 7, a, b);
                }
            }
            cluster_bar();   // Ba
            // G3: single-warp softmax per lane (warp 0 = lane0, warp 8 = lane1)
            if (tid < 32 || (tid >= 256 && tid < 288)) {
                int ln = tid >> 8, t = tid & 31;
                const float* ap = sm + SM_ATTP + ln * 1024;
                float v0 = 0.f, v1 = 0.f, v2 = 0.f, v3 = 0.f;
                #pragma unroll
                for (int s = 0; s < 8; ++s) {
                    const float* a8 = ap + s * 128;
                    v0 += a8[t]; v1 += a8[32 + t]; v2 += a8[64 + t]; v3 += a8[96 + t];
                }
                float mx = fmaxf(fmaxf(v0, v1), fmaxf(v2, v3));
                #pragma unroll
                for (int o = 16; o > 0; o >>= 1) mx = fmaxf(mx, __shfl_xor_sync(0xffffffffu, mx, o));
                float e0 = __expf(v0 - mx), e1 = __expf(v1 - mx);
                float e2 = __expf(v2 - mx), e3 = __expf(v3 - mx);
                float s = e0 + e1 + e2 + e3;
                #pragma unroll
                for (int o = 16; o > 0; o >>= 1) s += __shfl_xor_sync(0xffffffffu, s, o);
                float* at = sm + SM_ATT + ln * 128;
                at[t] = e0; at[32 + t] = e1; at[64 + t] = e2; at[96 + t] = e3;
                if (t == 0) sm[SM_RED + ln * 8] = 1.0f / s;
            }
            __syncthreads();
            // G5: x chunk partials (8 m-segs x 25 d, 16 iters, per-lane threads)
            {
                int r = tid & 255;
                if (r < 200 && tid < 456) {
                    int ln = tid >> 8;
                    int seg = r / 25, d = r % 25;
                    const float* mp = (ln ? mem1 : mem0) + (seg * 16) * MPAD + d;
                    const float* at = sm + SM_ATT + ln * 128 + seg * 16;
                    float a = 0.f;
                    #pragma unroll 8
                    for (int m = 0; m < 16; ++m) a += at[m] * mp[m * MPAD];
                    sm[SM_PART + ln * 1600 + seg * 25 + d] = a;
                }
            }
            __syncthreads();
            {
                int r = tid & 255;
                if (r < CH && tid < 256 + CH) {
                    int ln = tid >> 8;
                    const float* pp = sm + SM_PART + ln * 1600;
                    float a = 0.f;
                    #pragma unroll
                    for (int s = 0; s < 8; ++s) a += pp[s * 25 + r];
                    sm[SM_XV + ln * 32 + r] = a * sm[SM_RED + ln * 8];
                }
            }
            __syncthreads();
            // G6: fc1 GEMV, k-local (25 x-k + 25 q-k), dual-lane fused
            if (tid < 400) {
                int ks = tid / 200, c = tid % 200;
                const float* W = g_wTfc1 + (ks ? (200 + cbase) : cbase) * 200 + c;
                const float* a0p = sm + (ks ? SM_QL : SM_XV);
                const float* a1p = a0p + 32;
                float a0 = 0.f, a1 = 0.f;
                #pragma unroll 5
                for (int i = 0; i < CH; ++i) {
                    float w = W[i * 200];
                    a0 += a0p[i] * w;
                    a1 += a1p[i] * w;
                }
                sm[SM_PART + ks * 200 + c] = a0;
                sm[SM_PART + 1600 + ks * 200 + c] = a1;
            }
            __syncthreads();
            // G6b: deposit q partials to owner (both lanes)
            {
                int r = tid & 255;
                if (r < 200 && tid < 456) {
                    int ln = tid >> 8;
                    const float* pp = sm + SM_PART + ln * 1600;
                    float v = pp[r] + pp[200 + r];
                    int owner = r / CH, loc = r % CH;
                    uint32_t off = SM_QP + ln * 200 + rank * CH + loc;
                    if (owner == (int)rank) sm[off] = v;
                    else st_peer(sb + 4u * off, (uint32_t)owner, v);
                }
            }
            cluster_bar();   // Bq
            // G7: q chunk reduce (8 sources)
            {
                int r = tid & 255;
                if (r < CH && tid < 256 + CH) {
                    int ln = tid >> 8;
                    const float* qp = sm + SM_QP + ln * 200;
                    float a = bfc1s[r];
                    #pragma unroll
                    for (int s = 0; s < 8; ++s) a += qp[s * 25 + r];
                    sm[SM_QL + ln * 32 + r] = a;
                }
            }
            __syncthreads();
        }

        // ---- epilogue: z GEMV (k-local, single ks, dual-lane, direct deposit) ----
        if (tid < 200) {
            int c = tid;
            const float* W = g_wTfc + cbase * 200 + c;
            const float* q0 = sm + SM_QL;
            const float* q1 = q0 + 32;
            const float* s0 = mem0 + slot * MPAD;
            const float* s1 = mem1 + slot * MPAD;
            float a0 = 0.f, a1 = 0.f;
            #pragma unroll 5
            for (int i = 0; i < CH; ++i) {
                float w = W[i * 200];
                a0 += (q0[i] + s0[i]) * w;
                a1 += (q1[i] + s1[i]) * w;
            }
            int owner = c / CH, loc = c % CH;
            uint32_t off0 = SM_ZP + rank * CH + loc;
            uint32_t off1 = off0 + 200;
            if (owner == (int)rank) {
                sm[off0] = a0;
                sm[off1] = a1;
            } else {
                st_peer(sb + 4u * off0, (uint32_t)owner, a0);
                st_peer(sb + 4u * off1, (uint32_t)owner, a1);
            }
        } else if (tid >= 448 && tid < 498) {
            int ln = (tid - 448) / CH, t = (tid - 448) % CH;
            out[((lane0 + ln) * JJ + j) * DD + cbase + t] = sm[SM_QL + ln * 32 + t];
        }
        cluster_bar();   // Bz
        {
            int r = tid & 255;
            if (r < CH && tid < 256 + CH) {
                int ln = tid >> 8;
                const float* zp = sm + SM_ZP + ln * 200;
                float a = 2.0f * bfcs[r];
                #pragma unroll
                for (int s = 0; s < 8; ++s) a += zp[s * 25 + r];
                float z = tanhf(a);
                float* mslot = (ln ? mem1 : mem0) + slot * MPAD;
                mslot[r] *= z;
            }
        }
        __syncthreads();
    }
}

extern "C" void kernel_launch(void* const* d_in, const int* in_sizes, int n_in,
                              void* d_out, int out_size)
{
    const float* cosp  = (const float*)d_in[0];
    const float* bank  = (const float*)d_in[1];
    const float* mem_a = (const float*)d_in[2];
    const float* mem_b = (const float*)d_in[3];
    const float* w_fc  = (const float*)d_in[4];
    const float* b_fc  = (const float*)d_in[5];
    const float* w_fc1 = (const float*)d_in[6];
    const float* b_fc1 = (const float*)d_in[7];
    const float* w_ih  = (const float*)d_in[8];
    const float* w_hh  = (const float*)d_in[9];
    const float* b_ih  = (const float*)d_in[10];
    const float* b_hh  = (const float*)d_in[11];
    float* out = (float*)d_out;

    prep_kernel<<<148, 256>>>(w_fc, w_fc1, w_ih, w_hh, b_ih, b_hh);

    size_t smem_bytes = SM_TOT * sizeof(float);
    cudaFuncSetAttribute(speaker_kernel, cudaFuncAttributeMaxDynamicSharedMemorySize,
                         (int)smem_bytes);
    speaker_kernel<<<(BB / 2) * CSZ, NTH, smem_bytes>>>(cosp, bank, mem_a, mem_b,
                                                        b_fc, b_fc1, out);
}

// round 9
// speedup vs baseline: 2.0297x; 2.0297x over previous
#include <cuda_runtime.h>
#include <cstdint>

#define BB 32
#define JJ 256
#define MM 128
#define DD 200
#define NTH 512
#define CH 50            // d-chunk per rank
#define CSZ 4            // cluster size
#define MP 53            // padded mem chunk row stride (conflict-free column walks)

// ---------------- persistent transposed weight scratch (fp32) ----------------
__device__ __align__(16) float g_wTg[400 * 800];   // [k][4*d+g], k<200 ih else hh
__device__ __align__(16) float g_wTfc1[400 * 200]; // [k][d], k: x then q
__device__ __align__(16) float g_wTfc[200 * 200];  // [k][d]
__device__ __align__(16) float g_bg[800];          // b_ih+b_hh gate-interleaved

__global__ void prep_kernel(const float* __restrict__ w_fc, const float* __restrict__ w_fc1,
                            const float* __restrict__ w_ih, const float* __restrict__ w_hh,
                            const float* __restrict__ b_ih, const float* __restrict__ b_hh)
{
    int stride = gridDim.x * blockDim.x;
    int i0 = blockIdx.x * blockDim.x + threadIdx.x;

    for (int idx = i0; idx < 400 * 800; idx += stride) {
        int k = idx / 800, rem = idx % 800;
        int d = rem >> 2, g = rem & 3;
        int o = g * 200 + d;
        g_wTg[idx] = (k < 200) ? w_ih[o * 200 + k] : w_hh[o * 200 + (k - 200)];
    }
    for (int idx = i0; idx < 800; idx += stride) {
        int d = idx >> 2, g = idx & 3;
        int o = g * 200 + d;
        g_bg[idx] = b_ih[o] + b_hh[o];
    }
    for (int idx = i0; idx < 400 * 200; idx += stride) {
        int k = idx / 200, d = idx % 200;
        g_wTfc1[idx] = w_fc1[d * 400 + k];
    }
    for (int idx = i0; idx < 200 * 200; idx += stride) {
        int k = idx / 200, d = idx % 200;
        g_wTfc[idx] = w_fc[d * 200 + k];
    }
}

__device__ __forceinline__ float sigf(float v) { return 1.0f / (1.0f + __expf(-v)); }
__device__ __forceinline__ float ftanh(float x) { return 1.0f - 2.0f / (__expf(2.0f * x) + 1.0f); }

__device__ __forceinline__ void cluster_bar()
{
    asm volatile("barrier.cluster.arrive.aligned;\n\t"
                 "barrier.cluster.wait.aligned;" ::: "memory");
}
__device__ __forceinline__ void st_peer(uint32_t laddr, uint32_t peer, float v)
{
    uint32_t r;
    asm volatile("mapa.shared::cluster.u32 %0, %1, %2;" : "=r"(r) : "r"(laddr), "r"(peer));
    asm volatile("st.shared::cluster.f32 [%0], %1;" :: "r"(r), "f"(v) : "memory");
}
__device__ __forceinline__ void st_peer_v4(uint32_t laddr, uint32_t peer, float4 v)
{
    uint32_t r;
    unsigned long long lo = (unsigned long long)__float_as_uint(v.x) |
                            ((unsigned long long)__float_as_uint(v.y) << 32);
    unsigned long long hi = (unsigned long long)__float_as_uint(v.z) |
                            ((unsigned long long)__float_as_uint(v.w) << 32);
    asm volatile("mapa.shared::cluster.u32 %0, %1, %2;" : "=r"(r) : "r"(laddr), "r"(peer));
    asm volatile("st.shared::cluster.b64 [%0], %1;" :: "r"(r), "l"(lo) : "memory");
    asm volatile("st.shared::cluster.b64 [%0+8], %1;" :: "r"(r), "l"(hi) : "memory");
}

// ---------------- SMEM layout (float indices) ----------------
#define SM_MEM   0                      // mem[2 bank][128][MP] = 13568
#define SM_GP    13568                  // gparts[4 src][200] = 800
#define SM_ATTP  14368                  // attp[4 src][128] = 512
#define SM_QP    14880                  // qparts[4][50] = 200
#define SM_ZP    15080                  // zparts[4][50] = 200
#define SM_PART  15280                  // part scratch 3200 (4 ksplit x 200 float4)
#define SM_ATT   18480                  // att[128]
#define SM_RED   18608                  // red[8]
#define SM_XV    18616                  // xv[56]
#define SM_CS    18672                  // cstage[2][128] = 256
#define SM_BJ    18928                  // bstage[2][200] = 400
#define SM_QL    19328                  // qloc[56]
#define SM_HL    19384                  // hloc[56]
#define SM_CV    19440                  // cvec[56]
#define SM_BG    19496                  // bgs[224]
#define SM_BFC   19720                  // bfcs[56]
#define SM_BFC1  19776                  // bfc1s[56]
#define SM_WFC1  19832                  // wfc1 slice [100 rows][200] = 20000 (80 KB)
#define SM_WZ    39832                  // z-fc slice [50 rows][200] = 10000 (40 KB)
#define SM_TOT   49832                  // 199328 bytes

__global__ void __launch_bounds__(NTH, 1) __cluster_dims__(CSZ, 1, 1)
speaker_kernel(const float* __restrict__ cosp, const float* __restrict__ bank,
               const float* __restrict__ mem_a, const float* __restrict__ mem_b,
               const float* __restrict__ b_fc, const float* __restrict__ b_fc1,
               float* __restrict__ out)
{
    extern __shared__ float sm[];
    float* gparts = sm + SM_GP;
    float* attp   = sm + SM_ATTP;
    float* qparts = sm + SM_QP;
    float* zparts = sm + SM_ZP;
    float* part   = sm + SM_PART;
    float* att    = sm + SM_ATT;
    float* red    = sm + SM_RED;
    float* xv     = sm + SM_XV;
    float* qloc   = sm + SM_QL;
    float* hloc   = sm + SM_HL;
    float* cvec   = sm + SM_CV;
    float* bgs    = sm + SM_BG;
    float* bfcs   = sm + SM_BFC;
    float* bfc1s  = sm + SM_BFC1;
    float* wfc1s  = sm + SM_WFC1;
    float* wzs    = sm + SM_WZ;

    const int tid  = threadIdx.x;
    const int lane = blockIdx.x >> 2;      // batch index
    const uint32_t rank = blockIdx.x & 3;  // owns d-chunk [50r, 50r+50)
    const int cbase = (int)rank * CH;
    const uint32_t sb = (uint32_t)__cvta_generic_to_shared(sm);

    // ---- init: biases, mem chunks, weight caches, first-step staging ----
    if (tid < 224) bgs[tid] = g_bg[rank * 200 + min(tid, 199)];
    if (tid < CH) { bfcs[tid] = b_fc[cbase + tid]; bfc1s[tid] = b_fc1[cbase + tid]; }
    for (int idx = tid; idx < MM * CH; idx += NTH) {
        int m = idx / CH, d = idx % CH;
        sm[SM_MEM + m * MP + d]         = mem_a[lane * MM * DD + m * DD + cbase + d];
        sm[SM_MEM + MM * MP + m * MP + d] = mem_b[lane * MM * DD + m * DD + cbase + d];
    }
    // fc1 slice: local rows 0..49 -> global rows cbase..; 50..99 -> 200+cbase..
    for (int idx = tid; idx < 20000; idx += NTH) {
        int rr = idx / 200, c = idx % 200;
        int grow = (rr < 50) ? (cbase + rr) : (200 + cbase + rr - 50);
        wfc1s[idx] = g_wTfc1[grow * 200 + c];
    }
    // z-fc slice: rows cbase..cbase+49
    for (int idx = tid; idx < 10000; idx += NTH) {
        int rr = idx / 200, c = idx % 200;
        wzs[idx] = g_wTfc[(cbase + rr) * 200 + c];
    }
    if (tid < MM) sm[SM_CS + tid] = cosp[(lane * JJ + 0) * MM + tid];
    if (tid < DD) sm[SM_BJ + tid] = bank[(0 * BB + lane) * DD + tid];
    __syncthreads();
    cluster_bar();

    for (int j = 0; j < JJ; ++j) {
        const int flag = j & 1;
        const int slot = j >> 1;
        const int jb = j & 1;
        float* mem = sm + SM_MEM + flag * (MM * MP);
        const float* csj = sm + SM_CS + jb * 128;
        const float* bjj = sm + SM_BJ + jb * 200;

        // ---- P1: q-init GEMV (col-split, 8 ks x 50 c) + h-init partials ----
        if (tid < 400) {
            int ks = tid / 50, c = tid % 50;
            int k0 = ks * 25;
            const float* W = g_wTfc + cbase + c;
            float a = 0.f;
            #pragma unroll 5
            for (int i = 0; i < 25; ++i) a += bjj[k0 + i] * W[(k0 + i) * 200];
            part[ks * 50 + c] = a;
        } else if (tid < 500) {
            int t = tid - 400, seg = t / 50, d = t % 50;
            float a = 0.f;
            const float* mp = mem + (seg * 64) * MP + d;
            #pragma unroll 8
            for (int m = 0; m < 64; ++m) a += csj[seg * 64 + m] * mp[m * MP];
            part[400 + seg * 50 + d] = a;
        }
        __syncthreads();
        // ---- P2: combine q / combine h / reset c ----
        if (tid < CH) {
            float a = bfcs[tid];
            #pragma unroll
            for (int ks = 0; ks < 8; ++ks) a += part[ks * 50 + tid];
            qloc[tid] = a;
            cvec[tid] = 0.0f;
        } else if (tid >= 64 && tid < 64 + CH) {
            int t = tid - 64;
            hloc[t] = part[400 + t] + part[450 + t];
        }
        __syncthreads();

        // ---------------- inner loop P=3 ----------------
        for (int p = 0; p < 3; ++p) {
            // G0: gates GEMV, 4-way k-split (25-deep chains), 2 float4 cols/thread.
            // ks: 0=q[0:25), 1=q[25:50), 2=h[0:25), 3=h[25:50)
            if (tid < 400) {
                int ks = tid / 100, cp = tid % 100;
                int krow = (ks < 2 ? cbase : 200 + cbase) + (ks & 1) * 25;
                const float* act = (ks < 2 ? qloc : hloc) + (ks & 1) * 25;
                const float4* W4 = reinterpret_cast<const float4*>(g_wTg)
                                   + krow * 200 + cp * 2;
                float4 s0 = make_float4(0.f, 0.f, 0.f, 0.f);
                float4 s1 = make_float4(0.f, 0.f, 0.f, 0.f);
                #pragma unroll 5
                for (int i = 0; i < 25; ++i) {
                    float v = act[i];
                    float4 w0 = W4[i * 200];
                    float4 w1 = W4[i * 200 + 1];
                    s0.x += v * w0.x; s0.y += v * w0.y; s0.z += v * w0.z; s0.w += v * w0.w;
                    s1.x += v * w1.x; s1.y += v * w1.y; s1.z += v * w1.z; s1.w += v * w1.w;
                }
                float4* p4 = reinterpret_cast<float4*>(part);
                p4[ks * 200 + cp * 2]     = s0;
                p4[ks * 200 + cp * 2 + 1] = s1;
            } else if (p == 0 && j + 1 < JJ) {
                int nj = j + 1, nb = nj & 1, t = tid - 400;
                for (int i = t; i < MM; i += 112)
                    sm[SM_CS + nb * 128 + i] = cosp[(lane * JJ + nj) * MM + i];
                for (int i = t; i < DD; i += 112)
                    sm[SM_BJ + nb * 200 + i] = bank[(nj * BB + lane) * DD + i];
            }
            __syncthreads();
            // G0b: combine 4 ks + deposit gate-quad to owning rank
            if (tid < 200) {
                const float4* p4 = reinterpret_cast<const float4*>(part);
                float4 a = p4[tid], b = p4[200 + tid], c4 = p4[400 + tid], d4 = p4[600 + tid];
                float4 v = make_float4(a.x + b.x + c4.x + d4.x,
                                       a.y + b.y + c4.y + d4.y,
                                       a.z + b.z + c4.z + d4.z,
                                       a.w + b.w + c4.w + d4.w);
                int owner = tid / CH, cq = tid % CH;
                uint32_t off = SM_GP + rank * 200 + cq * 4;
                if (owner == (int)rank) *reinterpret_cast<float4*>(sm + off) = v;
                else st_peer_v4(sb + 4u * off, (uint32_t)owner, v);
            }
            cluster_bar();   // Bg
            // G1: reduce 4 sources + LSTM (quad-parallel activations)
            if (tid < 224) {
                int t = min(tid, 199);
                int chl = t >> 2, gi = t & 3;
                float g = bgs[t];
                #pragma unroll
                for (int s = 0; s < 4; ++s) g += gparts[s * 200 + chl * 4 + gi];
                float val = (gi == 2) ? ftanh(g) : sigf(g);
                float ig = __shfl_sync(0xffffffffu, val, 0, 4);
                float fg = __shfl_sync(0xffffffffu, val, 1, 4);
                float gg = __shfl_sync(0xffffffffu, val, 2, 4);
                float og = __shfl_sync(0xffffffffu, val, 3, 4);
                if (tid < 200 && gi == 0) {
                    float cc = fg * cvec[chl] + ig * gg;
                    cvec[chl] = cc;
                    hloc[chl] = og * ftanh(cc);
                }
            }
            __syncthreads();
            // G2: attention logit partials over local d-chunk
            if (tid < 256) {
                int m = tid & 127, hf = tid >> 7;
                float a = 0.f;
                const float* mrow = mem + m * MP + hf * 25;
                const float* hseg = hloc + hf * 25;
                #pragma unroll 5
                for (int i = 0; i < 25; ++i) a += hseg[i] * mrow[i];
                part[hf * 128 + m] = a;
            }
            __syncthreads();
            // G2b: push logit partials to all peers
            if (tid < 128) {
                float a = part[tid] + part[128 + tid];
                uint32_t off = SM_ATTP + rank * 128 + tid;
                sm[off] = a;
                #pragma unroll
                for (uint32_t pr = 1; pr < CSZ; ++pr)
                    st_peer(sb + 4u * off, (rank + pr) & 3, a);
            }
            cluster_bar();   // Ba
            // G3: fused single-warp softmax (combine + max + exp + sum)
            if (tid < 32) {
                float v0 = attp[tid]      + attp[128 + tid] + attp[256 + tid] + attp[384 + tid];
                float v1 = attp[32 + tid] + attp[160 + tid] + attp[288 + tid] + attp[416 + tid];
                float v2 = attp[64 + tid] + attp[192 + tid] + attp[320 + tid] + attp[448 + tid];
                float v3 = attp[96 + tid] + attp[224 + tid] + attp[352 + tid] + attp[480 + tid];
                float mx = fmaxf(fmaxf(v0, v1), fmaxf(v2, v3));
                #pragma unroll
                for (int o = 16; o > 0; o >>= 1) mx = fmaxf(mx, __shfl_xor_sync(0xffffffffu, mx, o));
                float e0 = __expf(v0 - mx), e1 = __expf(v1 - mx);
                float e2 = __expf(v2 - mx), e3 = __expf(v3 - mx);
                float s = e0 + e1 + e2 + e3;
                #pragma unroll
                for (int o = 16; o > 0; o >>= 1) s += __shfl_xor_sync(0xffffffffu, s, o);
                att[tid] = e0; att[32 + tid] = e1; att[64 + tid] = e2; att[96 + tid] = e3;
                if (tid == 0) red[0] = 1.0f / s;
            }
            __syncthreads();
            // G5: x chunk partials (8 m-segs x 50 d, 16 iters)
            if (tid < 400) {
                int seg = tid / 50, d = tid % 50;
                float a = 0.f;
                const float* mp = mem + (seg * 16) * MP + d;
                #pragma unroll 8
                for (int m = 0; m < 16; ++m) a += att[seg * 16 + m] * mp[m * MP];
                part[seg * 50 + d] = a;
            }
            __syncthreads();
            if (tid < CH) {
                float a = 0.f;
                #pragma unroll
                for (int s = 0; s < 8; ++s) a += part[s * 50 + tid];
                xv[tid] = a * red[0];
            }
            __syncthreads();
            // G6: fc1 GEMV from SMEM cache, 4-way k-split, 2 cols/thread (float2)
            // ks: 0=x[0:25), 1=x[25:50), 2=q[0:25), 3=q[25:50); local rows = ks*25+i
            if (tid < 400) {
                int ks = tid / 100, cp = tid % 100;
                const float* act = (ks < 2 ? xv : qloc) + (ks & 1) * 25;
                const float2* W2 = reinterpret_cast<const float2*>(wfc1s + (ks * 25) * 200) + cp;
                float a0 = 0.f, a1 = 0.f;
                #pragma unroll 5
                for (int i = 0; i < 25; ++i) {
                    float v = act[i];
                    float2 w = W2[i * 100];
                    a0 += v * w.x;
                    a1 += v * w.y;
                }
                part[ks * 200 + cp * 2]     = a0;
                part[ks * 200 + cp * 2 + 1] = a1;
            }
            __syncthreads();
            // G6b: combine 4 ks + deposit q partials to owner
            if (tid < 200) {
                float v = part[tid] + part[200 + tid] + part[400 + tid] + part[600 + tid];
                int owner = tid / CH;
                uint32_t off = SM_QP + rank * CH + (tid % CH);
                if (owner == (int)rank) sm[off] = v;
                else st_peer(sb + 4u * off, (uint32_t)owner, v);
            }
            cluster_bar();   // Bq
            // G7: q chunk reduce
            if (tid < CH) {
                float a = bfc1s[tid];
                #pragma unroll
                for (int s = 0; s < 4; ++s) a += qparts[s * CH + tid];
                qloc[tid] = a;
            }
            __syncthreads();
        }

        // ---- epilogue: z GEMV from SMEM cache + out write ----
        if (tid < 400) {
            int ks = tid / 200, c = tid % 200;
            const float* W = wzs + (ks * 25) * 200 + c;
            const float* svp = mem + slot * MP + ks * 25;
            const float* qp  = qloc + ks * 25;
            float a = 0.f;
            #pragma unroll 5
            for (int i = 0; i < 25; ++i) a += (qp[i] + svp[i]) * W[i * 200];
            part[ks * 200 + c] = a;
        } else if (tid >= 448 && tid < 448 + CH) {
            int t = tid - 448;
            out[(lane * JJ + j) * DD + cbase + t] = qloc[t];
        }
        __syncthreads();
        if (tid < 200) {
            float v = part[tid] + part[200 + tid];
            int owner = tid / CH;
            uint32_t off = SM_ZP + rank * CH + (tid % CH);
            if (owner == (int)rank) sm[off] = v;
            else st_peer(sb + 4u * off, (uint32_t)owner, v);
        }
        cluster_bar();   // Bz
        if (tid < CH) {
            float a = 2.0f * bfcs[tid];
            #pragma unroll
            for (int s = 0; s < 4; ++s) a += zparts[s * CH + tid];
            float z = tanhf(a);
            mem[slot * MP + tid] *= z;
        }
        __syncthreads();
    }
}

extern "C" void kernel_launch(void* const* d_in, const int* in_sizes, int n_in,
                              void* d_out, int out_size)
{
    const float* cosp  = (const float*)d_in[0];
    const float* bank  = (const float*)d_in[1];
    const float* mem_a = (const float*)d_in[2];
    const float* mem_b = (const float*)d_in[3];
    const float* w_fc  = (const float*)d_in[4];
    const float* b_fc  = (const float*)d_in[5];
    const float* w_fc1 = (const float*)d_in[6];
    const float* b_fc1 = (const float*)d_in[7];
    const float* w_ih  = (const float*)d_in[8];
    const float* w_hh  = (const float*)d_in[9];
    const float* b_ih  = (const float*)d_in[10];
    const float* b_hh  = (const float*)d_in[11];
    float* out = (float*)d_out;

    prep_kernel<<<148, 256>>>(w_fc, w_fc1, w_ih, w_hh, b_ih, b_hh);

    size_t smem_bytes = SM_TOT * sizeof(float);
    cudaFuncSetAttribute(speaker_kernel, cudaFuncAttributeMaxDynamicSharedMemorySize,
                         (int)smem_bytes);
    speaker_kernel<<<BB * CSZ, NTH, smem_bytes>>>(cosp, bank, mem_a, mem_b, b_fc, b_fc1, out);
}